// round 1
// baseline (speedup 1.0000x reference)
#include <cuda_runtime.h>
#include <cuda_bf16.h>
#include <math.h>

// Problem constants
#define NTOK   8192      // B*T
#define DMODEL 1024
#define DFFN   4096
#define NEXP   8
#define TOPK   2
#define NSLOT  (NTOK*TOPK)

// ---------------- device scratch (no cudaMalloc allowed) ----------------
__device__ float g_h[(size_t)NSLOT * DFFN];     // 256 MB: relu(x@W1+b1) per slot
__device__ float g_yp[(size_t)NSLOT * DMODEL];  // 64 MB: per-slot scaled output
__device__ int   g_expert_count[NEXP];
__device__ int   g_expert_slots[NEXP][NTOK];
__device__ float g_slot_w[NSLOT];
__device__ float g_imp_sum[NEXP];
__device__ float g_z2_sum;

// ---------------- helpers: packed f32x2 FMA (sm_103a FFMA2 path) --------
__device__ __forceinline__ unsigned long long pack2(float a, float b) {
    unsigned long long r;
    asm("mov.b64 %0, {%1,%2};" : "=l"(r) : "f"(a), "f"(b));
    return r;
}
__device__ __forceinline__ void unpack2(unsigned long long p, float& a, float& b) {
    asm("mov.b64 {%0,%1}, %2;" : "=f"(a), "=f"(b) : "l"(p));
}

// ---------------- kernel 0: zero accumulators ----------------
__global__ void zero_kernel() {
    int t = threadIdx.x;
    if (t < NEXP) { g_expert_count[t] = 0; g_imp_sum[t] = 0.f; }
    if (t == 0)   g_z2_sum = 0.f;
}

// ---------------- kernel 1: router (one block per token) ----------------
__global__ __launch_bounds__(128) void router_kernel(
    const float* __restrict__ x, const float* __restrict__ Wr)
{
    const int t = blockIdx.x;
    const int tid = threadIdx.x;
    const float* xr = x + (size_t)t * DMODEL;

    float acc[NEXP];
    #pragma unroll
    for (int e = 0; e < NEXP; e++) acc[e] = 0.f;

    for (int d = tid; d < DMODEL; d += 128) {
        float xv = xr[d];
        const float4* w4 = (const float4*)(Wr + (size_t)d * NEXP);
        float4 wa = w4[0], wb = w4[1];
        acc[0] += xv * wa.x; acc[1] += xv * wa.y;
        acc[2] += xv * wa.z; acc[3] += xv * wa.w;
        acc[4] += xv * wb.x; acc[5] += xv * wb.y;
        acc[6] += xv * wb.z; acc[7] += xv * wb.w;
    }

    __shared__ float s[NEXP][128];
    #pragma unroll
    for (int e = 0; e < NEXP; e++) s[e][tid] = acc[e];
    __syncthreads();
    for (int off = 64; off > 0; off >>= 1) {
        if (tid < off) {
            #pragma unroll
            for (int e = 0; e < NEXP; e++) s[e][tid] += s[e][tid + off];
        }
        __syncthreads();
    }

    if (tid == 0) {
        float lg[NEXP];
        #pragma unroll
        for (int e = 0; e < NEXP; e++) lg[e] = s[e][0];

        // softmax over all experts (for importance) + logsumexp (for z-loss)
        float mx = lg[0];
        #pragma unroll
        for (int e = 1; e < NEXP; e++) mx = fmaxf(mx, lg[e]);
        float ex[NEXP], ps = 0.f;
        #pragma unroll
        for (int e = 0; e < NEXP; e++) { ex[e] = expf(lg[e] - mx); ps += ex[e]; }
        float inv = 1.f / ps;
        #pragma unroll
        for (int e = 0; e < NEXP; e++) atomicAdd(&g_imp_sum[e], ex[e] * inv);
        float z = mx + logf(ps);
        atomicAdd(&g_z2_sum, z * z);

        // top-2, jax tie semantics (lowest index wins on ties)
        int i0 = 0; float v0 = lg[0];
        #pragma unroll
        for (int e = 1; e < NEXP; e++) if (lg[e] > v0) { v0 = lg[e]; i0 = e; }
        int i1 = -1; float v1 = -1e30f;
        #pragma unroll
        for (int e = 0; e < NEXP; e++) {
            if (e == i0) continue;
            if (lg[e] > v1) { v1 = lg[e]; i1 = e; }
        }
        float r = expf(v1 - v0);
        float w0 = 1.f / (1.f + r);
        float w1 = r / (1.f + r);

        int slot0 = t * 2, slot1 = t * 2 + 1;
        g_slot_w[slot0] = w0;
        g_slot_w[slot1] = w1;
        int p0 = atomicAdd(&g_expert_count[i0], 1);
        g_expert_slots[i0][p0] = slot0;
        int p1 = atomicAdd(&g_expert_count[i1], 1);
        g_expert_slots[i1][p1] = slot1;
    }
}

// ---------------- GEMM: 128x128x16 fp32 tiles, packed f32x2 FMA ----------
// MODE 1: A = x (row = slot>>1), B = W1[e] (K=1024, N=4096), C = g_h, epilogue relu(.+b1)
// MODE 2: A = g_h (row = slot),  B = W2[e] (K=4096, N=1024), C = g_yp, epilogue (.+b2)*w
#define TM 128
#define TN 128
#define TK 16

template<int MODE>
__global__ __launch_bounds__(256) void moe_gemm(
    const float* __restrict__ Aext,
    const float* __restrict__ Bg,
    const float* __restrict__ biasg)
{
    constexpr int NDIM = (MODE == 1) ? DFFN : DMODEL;
    constexpr int KDIM = (MODE == 1) ? DMODEL : DFFN;

    const int e = blockIdx.z;
    const int count = g_expert_count[e];
    const int m0 = blockIdx.y * TM;
    if (m0 >= count) return;
    const int n0 = blockIdx.x * TN;

    const int* slots = g_expert_slots[e];
    const float* A = (MODE == 1) ? Aext : (const float*)g_h;
    float* C = (MODE == 1) ? (float*)g_h : (float*)g_yp;
    const float* B = Bg + (size_t)e * KDIM * NDIM;
    const float* bias = biasg + (size_t)e * NDIM;

    const int tid = threadIdx.x;
    const int tx = tid & 15, ty = tid >> 4;

    __shared__ float As[2][TK][TM];
    __shared__ float Bs[2][TK][TN];

    // Per-thread A-load assignment: 2 float4 loads (rows fixed across k-tiles)
    int arow[2], acol[2];
    const float* aptr[2];
    #pragma unroll
    for (int s = 0; s < 2; s++) {
        int lin = tid + s * 256;  // float4 index in 128x16 tile
        int m = lin >> 2, q = lin & 3;
        arow[s] = m; acol[s] = q * 4;
        int gm = m0 + m;
        if (gm < count) {
            int slot = slots[gm];
            int row = (MODE == 1) ? (slot >> 1) : slot;
            aptr[s] = A + (size_t)row * KDIM + q * 4;
        } else {
            aptr[s] = nullptr;
        }
    }

    float4 areg[2], breg[2];

    auto loadA = [&](int kt) {
        int k0 = kt * TK;
        #pragma unroll
        for (int s = 0; s < 2; s++)
            areg[s] = aptr[s] ? *(const float4*)(aptr[s] + k0)
                              : make_float4(0.f, 0.f, 0.f, 0.f);
    };
    auto loadB = [&](int kt) {
        int k0 = kt * TK;
        #pragma unroll
        for (int s = 0; s < 2; s++) {
            int lin = tid + s * 256;
            int n4 = lin & 31, k = lin >> 5;
            breg[s] = *(const float4*)(B + (size_t)(k0 + k) * NDIM + n0 + n4 * 4);
        }
    };
    auto storeAB = [&](int buf) {
        #pragma unroll
        for (int s = 0; s < 2; s++) {
            As[buf][acol[s] + 0][arow[s]] = areg[s].x;
            As[buf][acol[s] + 1][arow[s]] = areg[s].y;
            As[buf][acol[s] + 2][arow[s]] = areg[s].z;
            As[buf][acol[s] + 3][arow[s]] = areg[s].w;
            int lin = tid + s * 256;
            int n4 = lin & 31, k = lin >> 5;
            *(float4*)&Bs[buf][k][n4 * 4] = breg[s];
        }
    };

    unsigned long long acc[8][4] = {};  // (0.f,0.f) packed == 0

    const int NT = KDIM / TK;
    loadA(0); loadB(0);
    storeAB(0);
    __syncthreads();

    for (int kt = 0; kt < NT; kt++) {
        int cur = kt & 1;
        if (kt + 1 < NT) { loadA(kt + 1); loadB(kt + 1); }
        #pragma unroll
        for (int k = 0; k < TK; k++) {
            float4 a0 = *(const float4*)&As[cur][k][ty * 8];
            float4 a1 = *(const float4*)&As[cur][k][ty * 8 + 4];
            float4 b0 = *(const float4*)&Bs[cur][k][tx * 8];
            float4 b1 = *(const float4*)&Bs[cur][k][tx * 8 + 4];
            unsigned long long bp[4];
            bp[0] = pack2(b0.x, b0.y); bp[1] = pack2(b0.z, b0.w);
            bp[2] = pack2(b1.x, b1.y); bp[3] = pack2(b1.z, b1.w);
            float av[8] = {a0.x, a0.y, a0.z, a0.w, a1.x, a1.y, a1.z, a1.w};
            #pragma unroll
            for (int i = 0; i < 8; i++) {
                unsigned long long ap = pack2(av[i], av[i]);
                #pragma unroll
                for (int j = 0; j < 4; j++)
                    asm("fma.rn.f32x2 %0, %1, %2, %0;"
                        : "+l"(acc[i][j]) : "l"(ap), "l"(bp[j]));
            }
        }
        if (kt + 1 < NT) storeAB((kt + 1) & 1);
        __syncthreads();
    }

    // Epilogue
    #pragma unroll
    for (int i = 0; i < 8; i++) {
        int gm = m0 + ty * 8 + i;
        if (gm >= count) continue;
        int slot = slots[gm];
        float w = (MODE == 2) ? g_slot_w[slot] : 0.f;
        float out[8];
        #pragma unroll
        for (int j = 0; j < 4; j++) unpack2(acc[i][j], out[2 * j], out[2 * j + 1]);
        int gn = n0 + tx * 8;
        #pragma unroll
        for (int j = 0; j < 8; j++) {
            float v = out[j] + bias[gn + j];
            if (MODE == 1) v = fmaxf(v, 0.f);
            else           v *= w;
            out[j] = v;
        }
        float4* dst = (float4*)&C[(size_t)slot * NDIM + gn];
        dst[0] = make_float4(out[0], out[1], out[2], out[3]);
        dst[1] = make_float4(out[4], out[5], out[6], out[7]);
    }
}

// ---------------- combine: y[t] = yp[2t] + yp[2t+1] ----------------
__global__ __launch_bounds__(256) void combine_kernel(float* __restrict__ y)
{
    // float4 granularity: token t, quad d4
    int i = blockIdx.x * blockDim.x + threadIdx.x;   // 0 .. NTOK*256-1
    int t = i >> 8;
    int d4 = i & 255;
    const float4* yp = (const float4*)g_yp;
    float4 a = yp[(size_t)(2 * t) * 256 + d4];
    float4 b = yp[(size_t)(2 * t + 1) * 256 + d4];
    ((float4*)y)[(size_t)t * 256 + d4] =
        make_float4(a.x + b.x, a.y + b.y, a.z + b.z, a.w + b.w);
}

// ---------------- finalize: counts / fraction / aux_loss ----------------
__global__ void finalize_kernel(float* __restrict__ out)
{
    if (threadIdx.x != 0) return;
    const size_t Y = (size_t)NTOK * DMODEL;
    float total = 0.f;
    float c[NEXP];
    #pragma unroll
    for (int e = 0; e < NEXP; e++) { c[e] = (float)g_expert_count[e]; total += c[e]; }
    float denom = fmaxf(total, 1.f);
    float lb = 0.f;
    #pragma unroll
    for (int e = 0; e < NEXP; e++) {
        out[Y + e] = c[e];
        out[Y + NEXP + e] = c[e] / denom;
        float imp = g_imp_sum[e] / (float)NTOK;
        lb += imp * imp;
    }
    float lb_loss = (float)NEXP * lb * 0.01f;
    float z_loss  = (g_z2_sum / (float)NTOK) * 0.001f;
    out[Y + 2 * NEXP] = lb_loss + z_loss;
}

// ---------------- launch ----------------
extern "C" void kernel_launch(void* const* d_in, const int* in_sizes, int n_in,
                              void* d_out, int out_size)
{
    const float* x  = (const float*)d_in[0];
    const float* Wr = (const float*)d_in[1];
    const float* W1 = (const float*)d_in[2];
    const float* b1 = (const float*)d_in[3];
    const float* W2 = (const float*)d_in[4];
    const float* b2 = (const float*)d_in[5];
    float* out = (float*)d_out;

    zero_kernel<<<1, 32>>>();
    router_kernel<<<NTOK, 128>>>(x, Wr);

    // GEMM1: M<=8192 per expert, N=4096, K=1024
    moe_gemm<1><<<dim3(DFFN / TN, NTOK / TM, NEXP), 256>>>(x, W1, b1);
    // GEMM2: M<=8192 per expert, N=1024, K=4096
    moe_gemm<2><<<dim3(DMODEL / TN, NTOK / TM, NEXP), 256>>>(nullptr, W2, b2);

    combine_kernel<<<(NTOK * 256) / 256, 256>>>(out);
    finalize_kernel<<<1, 32>>>(out);
}